// round 14
// baseline (speedup 1.0000x reference)
#include <cuda_runtime.h>
#include <cuda_fp16.h>
#include <cstdint>

#define NN    8192
#define IND   512
#define OUTD  256
#define BM    64
#define BK    64
#define KS     4                   // K slices per row block
#define KRANGE (NN / KS)           // 2048
#define KTILES (KRANGE / BK)       // 32
#define NITEMS ((NN / BM) * KS)    // 512
#define NCTAS  296                 // 2 per SM on 148 SMs
#define LOG2E 1.4426950408889634f

// ---- fused kernel dynamic smem (bytes) ----
#define SP_OFF   0
#define SP_BUF   8192
#define SH_OFF   16384
#define SH_BUF   32768
#define SER_OFF  81920             // 3 x 512B
#define ITEM_OFF 83456
#define SMEM_FUSED 83472           // 2 CTAs/SM

// XOR swizzle: 16B chunk cb within a row, rotated by row&7
#define SWZ(row, cb) ((((cb) ^ ((row) & 7))) * 16)

// ---------------- scratch ----------------
__device__ __half    g_h16[(size_t)NN * OUTD];            // h fp16 row-major
__device__ __half    g_xh[(size_t)NN * IND];              // X fp16 (written by eler)
__device__ __half    g_wh[(size_t)IND * OUTD];            // W fp16 (written by u)
__device__ float     g_part[(size_t)KS * NN * OUTD];      // split-K partial numerators
__device__ float     g_Lp[KS * NN];                       // split-K partial rowsums
__device__ __align__(16) float2 g_elx[NN];
__device__ __align__(16) float2 g_erx[NN];
__device__ float     g_ul[IND];
__device__ float     g_ur[IND];
__device__ float     g_cb[2];
__device__ uint32_t  g_ctr;                               // work-steal counter

// ---------------- helpers ----------------
__device__ __forceinline__ uint32_t smem_u32(const void* p) {
    return (uint32_t)__cvta_generic_to_shared(p);
}
__device__ __forceinline__ void cp16(void* dst, const void* src) {
    asm volatile("cp.async.cg.shared.global [%0], [%1], 16;" ::
                 "r"(smem_u32(dst)), "l"(src) : "memory");
}
__device__ __forceinline__ void cp_commit() {
    asm volatile("cp.async.commit_group;" ::: "memory");
}
__device__ __forceinline__ void cp_wait0() {
    asm volatile("cp.async.wait_group 0;" ::: "memory");
}
__device__ __forceinline__ float ex2f(float x) {
    float y; asm("ex2.approx.ftz.f32 %0, %1;" : "=f"(y) : "f"(x)); return y;
}
__device__ __forceinline__ uint32_t pack2h(float a, float b) {
    __half2 h = __floats2half2_rn(a, b);
    return *reinterpret_cast<uint32_t*>(&h);
}
__device__ __forceinline__ void ldmA(uint32_t* r, const void* p) {
    uint32_t a = smem_u32(p);
    asm volatile("ldmatrix.sync.aligned.m8n8.x4.shared.b16 {%0,%1,%2,%3}, [%4];"
                 : "=r"(r[0]), "=r"(r[1]), "=r"(r[2]), "=r"(r[3]) : "r"(a));
}
__device__ __forceinline__ void ldmBT(uint32_t* r, const void* p) {
    uint32_t a = smem_u32(p);
    asm volatile("ldmatrix.sync.aligned.m8n8.x4.trans.shared.b16 {%0,%1,%2,%3}, [%4];"
                 : "=r"(r[0]), "=r"(r[1]), "=r"(r[2]), "=r"(r[3]) : "r"(a));
}
__device__ __forceinline__ void mma16816(float* c, const uint32_t* a,
                                         uint32_t b0, uint32_t b1) {
    asm volatile(
        "mma.sync.aligned.m16n8k16.row.col.f32.f16.f16.f32 "
        "{%0,%1,%2,%3},{%4,%5,%6,%7},{%8,%9},{%0,%1,%2,%3};"
        : "+f"(c[0]), "+f"(c[1]), "+f"(c[2]), "+f"(c[3])
        : "r"(a[0]), "r"(a[1]), "r"(a[2]), "r"(a[3]), "r"(b0), "r"(b1));
}

// ---------------- kernel 0: zero the work counter (per replay) ----------------
__global__ void zero_ctr_kernel() { g_ctr = 0; }

// ---------------- kernel 1: u vectors + W -> fp16 ----------------
__global__ void __launch_bounds__(256) u_kernel(const float* __restrict__ W,
                                                const float* __restrict__ b,
                                                const float* __restrict__ a,
                                                const float* __restrict__ ab) {
    __shared__ float sa[2 * OUTD];
    const int tid = threadIdx.x;
    sa[tid]       = a[tid];
    sa[tid + 256] = a[tid + 256];
    __syncthreads();
    const int lane = tid & 31;
    const int k    = blockIdx.x * 8 + (tid >> 5);
    const float* wr = W + (size_t)k * OUTD + lane * 8;
    float4 v0 = *(const float4*)(wr);
    float4 v1 = *(const float4*)(wr + 4);
    {
        uint4 wq;
        wq.x = pack2h(v0.x, v0.y);
        wq.y = pack2h(v0.z, v0.w);
        wq.z = pack2h(v1.x, v1.y);
        wq.w = pack2h(v1.z, v1.w);
        *(uint4*)(g_wh + (size_t)k * OUTD + lane * 8) = wq;
    }
    const float* s0 = sa + lane * 8;
    const float* s1 = sa + OUTD + lane * 8;
    float ul = v0.x * s0[0] + v0.y * s0[1] + v0.z * s0[2] + v0.w * s0[3]
             + v1.x * s0[4] + v1.y * s0[5] + v1.z * s0[6] + v1.w * s0[7];
    float ur = v0.x * s1[0] + v0.y * s1[1] + v0.z * s1[2] + v0.w * s1[3]
             + v1.x * s1[4] + v1.y * s1[5] + v1.z * s1[6] + v1.w * s1[7];
    #pragma unroll
    for (int o = 16; o > 0; o >>= 1) {
        ul += __shfl_xor_sync(0xffffffffu, ul, o);
        ur += __shfl_xor_sync(0xffffffffu, ur, o);
    }
    if (lane == 0) { g_ul[k] = ul; g_ur[k] = ur; }
    if (blockIdx.x == 0 && tid == 0) {
        float bl = 0.f, br = 0.f;
        for (int n = 0; n < OUTD; ++n) {
            bl += b[n] * sa[n];
            br += b[n] * sa[OUTD + n];
        }
        g_cb[0] = bl + ab[0];
        g_cb[1] = br;
    }
}

// ---------------- kernel 2: el/er exps + X -> fp16 ----------------
__global__ void __launch_bounds__(256) eler_kernel(const float* __restrict__ X) {
    __shared__ float sul[IND], sur[IND];
    const int tid = threadIdx.x;
    sul[tid]       = g_ul[tid];
    sul[tid + 256] = g_ul[tid + 256];
    sur[tid]       = g_ur[tid];
    sur[tid + 256] = g_ur[tid + 256];
    __syncthreads();
    const int lane = tid & 31;
    const int w    = tid >> 5;
    const int i    = blockIdx.x * 8 + w;
    const float* xr = X + (size_t)i * IND;
    float dl = 0.f, dr = 0.f;
    #pragma unroll
    for (int q = 0; q < 4; ++q) {
        int c = q * 128 + lane * 4;
        float4 v = *(const float4*)(xr + c);
        uint2 xq;
        xq.x = pack2h(v.x, v.y);
        xq.y = pack2h(v.z, v.w);
        *(uint2*)(g_xh + (size_t)i * IND + c) = xq;
        dl += v.x * sul[c] + v.y * sul[c + 1] + v.z * sul[c + 2] + v.w * sul[c + 3];
        dr += v.x * sur[c] + v.y * sur[c + 1] + v.z * sur[c + 2] + v.w * sur[c + 3];
    }
    #pragma unroll
    for (int o = 16; o > 0; o >>= 1) {
        dl += __shfl_xor_sync(0xffffffffu, dl, o);
        dr += __shfl_xor_sync(0xffffffffu, dr, o);
    }
    if (lane == 0) {
        float el = dl + g_cb[0];
        float er = dr + g_cb[1];
        float2 ev, fv;
        ev.x = ex2f(el * LOG2E - 3.0f);
        ev.y = ex2f(el * (0.2f * LOG2E) - 3.0f);
        fv.x = ex2f(er * LOG2E - 3.0f);
        fv.y = ex2f(er * (0.2f * LOG2E) - 3.0f);
        g_elx[i] = ev;
        g_erx[i] = fv;
    }
}

// ---------------- kernel 3: gemm1 v3 — 64x64 tiles, 512 CTAs, fp16 pipeline ----
#define G1_SMEM 32768
__global__ void __launch_bounds__(128, 4) gemm1_kernel(const float* __restrict__ b) {
    extern __shared__ __align__(1024) char smem[];
    char* sX = smem;
    char* sW = smem + 16384;

    const int tid  = threadIdx.x;
    const int lane = tid & 31;
    const int wid  = tid >> 5;
    const int mblk = blockIdx.x * 64;
    const int nblk = blockIdx.y * 64;
    const int wm   = (wid >> 1) * 32;
    const int wn   = (wid & 1) * 32;

    float acc[2][4][4];
    #pragma unroll
    for (int i = 0; i < 2; ++i)
        #pragma unroll
        for (int j = 0; j < 4; ++j)
            #pragma unroll
            for (int k = 0; k < 4; ++k) acc[i][j][k] = 0.f;

    #pragma unroll
    for (int p = 0; p < 4; ++p) {
        int idx = p * 128 + tid;
        int row = idx >> 3, cb = idx & 7;
        cp16(sX + row * 128 + SWZ(row, cb),
             g_xh + (size_t)(mblk + row) * IND + cb * 8);
        cp16(sW + row * 128 + SWZ(row, cb),
             g_wh + (size_t)row * OUTD + nblk + cb * 8);
    }
    cp_commit();

    for (int ki = 0; ki < IND / BK; ++ki) {
        cp_wait0();
        __syncthreads();

        if (ki + 1 < IND / BK) {
            const int k0 = (ki + 1) * BK;
            const int nb = (ki + 1) & 1;
            #pragma unroll
            for (int p = 0; p < 4; ++p) {
                int idx = p * 128 + tid;
                int row = idx >> 3, cb = idx & 7;
                cp16(sX + nb * 8192 + row * 128 + SWZ(row, cb),
                     g_xh + (size_t)(mblk + row) * IND + k0 + cb * 8);
                cp16(sW + nb * 8192 + row * 128 + SWZ(row, cb),
                     g_wh + (size_t)(k0 + row) * OUTD + nblk + cb * 8);
            }
            cp_commit();
        }

        const char* sXb = sX + (ki & 1) * 8192;
        const char* sWb = sW + (ki & 1) * 8192;
        #pragma unroll
        for (int kk = 0; kk < 4; ++kk) {
            uint32_t A[2][4];
            #pragma unroll
            for (int mf = 0; mf < 2; ++mf) {
                int prow = wm + mf * 16 + (lane & 15);
                ldmA(A[mf], sXb + prow * 128 + SWZ(prow, kk * 2 + (lane >> 4)));
            }
            const int krow = (kk << 4) + (lane & 15);
            const char* wb = sWb + krow * 128;
            #pragma unroll
            for (int nf = 0; nf < 2; ++nf) {
                uint32_t B[4];
                ldmBT(B, wb + SWZ(krow, (wn >> 3) + nf * 2 + (lane >> 4)));
                #pragma unroll
                for (int mf = 0; mf < 2; ++mf) {
                    mma16816(acc[mf][2 * nf],     A[mf], B[0], B[1]);
                    mma16816(acc[mf][2 * nf + 1], A[mf], B[2], B[3]);
                }
            }
        }
    }

    #pragma unroll
    for (int mf = 0; mf < 2; ++mf) {
        int grow = mblk + wm + mf * 16 + (lane >> 2);
        #pragma unroll
        for (int nf = 0; nf < 4; ++nf) {
            int gcol = nblk + wn + nf * 8 + (lane & 3) * 2;
            float b0 = b[gcol], b1 = b[gcol + 1];
            *(__half2*)&g_h16[(size_t)grow * OUTD + gcol] =
                __floats2half2_rn(acc[mf][nf][0] + b0, acc[mf][nf][1] + b1);
            *(__half2*)&g_h16[(size_t)(grow + 8) * OUTD + gcol] =
                __floats2half2_rn(acc[mf][nf][2] + b0, acc[mf][nf][3] + b1);
        }
    }
}

// ---------------- kernel 4: fused attention — persistent, work-stealing --------
__global__ void __launch_bounds__(256, 2) gat_fused_kernel(const int* __restrict__ adj) {
    extern __shared__ __align__(1024) char smem[];
    int* sItem = (int*)(smem + ITEM_OFF);

    const int tid  = threadIdx.x;
    const int lane = tid & 31;
    const int wid  = tid >> 5;

    const int r  = tid >> 2;           // 0..63 (P row owned by this thread)
    const int cq = tid & 3;            // col quarter
    const int cg = cq << 4;            // 0,16,32,48

    const int wm = (wid >> 2) * 32;    // MMA row group
    const int wn = (wid & 3) * 64;     // MMA col group

    for (;;) {
        __syncthreads();               // all warps done with previous item
        if (tid == 0) *sItem = (int)atomicAdd(&g_ctr, 1u);
        __syncthreads();
        const int item = *sItem;
        if (item >= NITEMS) return;

        const int rb = item >> 2;
        const int ks = item & 3;
        const int i0 = rb * BM;
        const int J0 = ks * KRANGE;
        const int* arow = adj + (size_t)(i0 + r) * NN + J0 + cg;
        const float2 ev = g_elx[i0 + r];

        // ---- prologue: adj[0] LDG; cp {H0, er0, er1}; compute P[0] ----
        int4 a[4];
        #pragma unroll
        for (int q = 0; q < 4; ++q) a[q] = __ldcs((const int4*)(arow + 4 * q));

        #pragma unroll
        for (int p = 0; p < 8; ++p) {
            int idx = p * 256 + tid;
            int row = idx >> 5, cb = idx & 31;
            cp16(smem + SH_OFF + row * 512 + SWZ(row, cb),
                 g_h16 + (size_t)(J0 + row) * OUTD + cb * 8);
        }
        if (tid < 32) {
            cp16(smem + SER_OFF + tid * 16,       g_erx + J0 + tid * 2);
            cp16(smem + SER_OFF + 512 + tid * 16, g_erx + J0 + BK + tid * 2);
        }
        cp_commit();
        cp_wait0();
        __syncthreads();

        float psum = 0.f;
        {
            const float4* se = (const float4*)(smem + SER_OFF);
            uint32_t pk[8];
            #pragma unroll
            for (int kk = 0; kk < 4; ++kk) {
                float4 f0 = se[(cg + 4 * kk) >> 1];
                float4 f1 = se[((cg + 4 * kk) >> 1) + 1];
                int4 av = a[kk];
                float p0 = fmaxf(ev.x * f0.x, ev.y * f0.y);
                float p1 = fmaxf(ev.x * f0.z, ev.y * f0.w);
                float p2 = fmaxf(ev.x * f1.x, ev.y * f1.y);
                float p3 = fmaxf(ev.x * f1.z, ev.y * f1.w);
                p0 = (av.x > 0) ? p0 : 0.f;
                p1 = (av.y > 0) ? p1 : 0.f;
                p2 = (av.z > 0) ? p2 : 0.f;
                p3 = (av.w > 0) ? p3 : 0.f;
                psum += (p0 + p1) + (p2 + p3);
                pk[2 * kk]     = pack2h(p0, p1);
                pk[2 * kk + 1] = pack2h(p2, p3);
            }
            char* pb = smem + SP_OFF + r * 128;
            *(uint4*)(pb + SWZ(r, 2 * cq))     = make_uint4(pk[0], pk[1], pk[2], pk[3]);
            *(uint4*)(pb + SWZ(r, 2 * cq + 1)) = make_uint4(pk[4], pk[5], pk[6], pk[7]);
        }

        float acc[2][8][4];
        #pragma unroll
        for (int i = 0; i < 2; ++i)
            #pragma unroll
            for (int j = 0; j < 8; ++j)
                #pragma unroll
                for (int k = 0; k < 4; ++k) acc[i][j][k] = 0.f;

        // ---- main loop over this item's 32 tiles ----
        for (int t = 0; t < KTILES; ++t) {
            cp_wait0();
            __syncthreads();   // H[t]/er ready; P[t] STS visible; MMA[t-1] done

            const bool more = (t + 1 < KTILES);

            if (more) {
                const int jn = J0 + (t + 1) * BK;
                #pragma unroll
                for (int p = 0; p < 8; ++p) {
                    int idx = p * 256 + tid;
                    int row = idx >> 5, cb = idx & 31;
                    cp16(smem + SH_OFF + ((t + 1) & 1) * SH_BUF + row * 512 + SWZ(row, cb),
                         g_h16 + (size_t)(jn + row) * OUTD + cb * 8);
                }
                if (t + 2 < KTILES && tid < 32)
                    cp16(smem + SER_OFF + ((t + 2) % 3) * 512 + tid * 16,
                         g_erx + J0 + (t + 2) * BK + tid * 2);
                cp_commit();
            }

            if (more) {
                const int4* an = (const int4*)(arow + (t + 1) * BK);
                #pragma unroll
                for (int q = 0; q < 4; ++q) a[q] = __ldcs(an + q);
            }

            const char*   sPb = smem + SP_OFF + (t & 1) * SP_BUF;
            const char*   sHb = smem + SH_OFF + (t & 1) * SH_BUF;
            const float4* se  = (const float4*)(smem + SER_OFF + ((t + 1) % 3) * 512);

            uint32_t pk[8];

            #pragma unroll
            for (int kk = 0; kk < 4; ++kk) {
                uint32_t A[2][4];
                #pragma unroll
                for (int mf = 0; mf < 2; ++mf) {
                    int prow = wm + mf * 16 + (lane & 15);
                    ldmA(A[mf], sPb + prow * 128 + SWZ(prow, kk * 2 + (lane >> 4)));
                }
                const int krow = (kk << 4) + (lane & 15);
                const char* hb = sHb + krow * 512;
                #pragma unroll
                for (int nf = 0; nf < 4; ++nf) {
                    uint32_t B[4];
                    ldmBT(B, hb + SWZ(krow, (wn >> 3) + nf * 2 + (lane >> 4)));
                    mma16816(acc[0][2 * nf],     A[0], B[0], B[1]);
                    mma16816(acc[0][2 * nf + 1], A[0], B[2], B[3]);
                    mma16816(acc[1][2 * nf],     A[1], B[0], B[1]);
                    mma16816(acc[1][2 * nf + 1], A[1], B[2], B[3]);
                }

                if (more) {
                    float4 f0 = se[(cg + 4 * kk) >> 1];
                    float4 f1 = se[((cg + 4 * kk) >> 1) + 1];
                    int4 av = a[kk];
                    float p0 = fmaxf(ev.x * f0.x, ev.y * f0.y);
                    float p1 = fmaxf(ev.x * f0.z, ev.y * f0.w);
                    float p2 = fmaxf(ev.x * f1.x, ev.y * f1.y);
                    float p3 = fmaxf(ev.x * f1.z, ev.y * f1.w);
                    p0 = (av.x > 0) ? p0 : 0.f;
                    p1 = (av.y > 0) ? p1 : 0.f;
                    p2 = (av.z > 0) ? p2 : 0.f;
                    p3 = (av.w > 0) ? p3 : 0.f;
                    psum += (p0 + p1) + (p2 + p3);
                    pk[2 * kk]     = pack2h(p0, p1);
                    pk[2 * kk + 1] = pack2h(p2, p3);
                }
            }

            if (more) {
                char* pb = smem + SP_OFF + ((t + 1) & 1) * SP_BUF + r * 128;
                *(uint4*)(pb + SWZ(r, 2 * cq))     = make_uint4(pk[0], pk[1], pk[2], pk[3]);
                *(uint4*)(pb + SWZ(r, 2 * cq + 1)) = make_uint4(pk[4], pk[5], pk[6], pk[7]);
            }
        }

        // ---- epilogue: rowsum + partial numerators for this item ----
        psum += __shfl_xor_sync(0xffffffffu, psum, 1);
        psum += __shfl_xor_sync(0xffffffffu, psum, 2);
        if ((tid & 3) == 0) g_Lp[ks * NN + i0 + r] = psum;

        #pragma unroll
        for (int mf = 0; mf < 2; ++mf) {
            int row0 = wm + mf * 16 + (lane >> 2);
            float* d0 = g_part + ((size_t)ks * NN + i0 + row0) * OUTD;
            float* d1 = g_part + ((size_t)ks * NN + i0 + row0 + 8) * OUTD;
            #pragma unroll
            for (int nf = 0; nf < 8; ++nf) {
                int col = wn + nf * 8 + (lane & 3) * 2;
                *(float2*)(d0 + col) = make_float2(acc[mf][nf][0], acc[mf][nf][1]);
                *(float2*)(d1 + col) = make_float2(acc[mf][nf][2], acc[mf][nf][3]);
            }
        }
    }
}

// ---------------- kernel 5: combine split-K partials (4 slices) ----------------
__global__ void __launch_bounds__(256) combine_kernel(float* __restrict__ out) {
    const int gid = blockIdx.x * 256 + threadIdx.x;
    const int row = gid >> 6;
    const int c   = (gid & 63) * 4;
    const size_t off = (size_t)row * OUTD + c;
    const float4 x0 = __ldcs((const float4*)(g_part + off));
    const float4 x1 = __ldcs((const float4*)(g_part + (size_t)NN * OUTD + off));
    const float4 x2 = __ldcs((const float4*)(g_part + (size_t)2 * NN * OUTD + off));
    const float4 x3 = __ldcs((const float4*)(g_part + (size_t)3 * NN * OUTD + off));
    const float inv = 1.0f / (g_Lp[row] + g_Lp[NN + row] +
                              g_Lp[2 * NN + row] + g_Lp[3 * NN + row]);
    float4 o;
    o.x = ((x0.x + x1.x) + (x2.x + x3.x)) * inv;
    o.y = ((x0.y + x1.y) + (x2.y + x3.y)) * inv;
    o.z = ((x0.z + x1.z) + (x2.z + x3.z)) * inv;
    o.w = ((x0.w + x1.w) + (x2.w + x3.w)) * inv;
    *(float4*)(out + off) = o;
}

// ---------------- launch ----------------
extern "C" void kernel_launch(void* const* d_in, const int* in_sizes, int n_in,
                              void* d_out, int out_size) {
    const int*   adj = (const int*)d_in[0];
    const float* X   = (const float*)d_in[1];
    const float* W   = (const float*)d_in[2];
    const float* b   = (const float*)d_in[3];
    const float* a   = (const float*)d_in[4];
    const float* ab  = (const float*)d_in[5];
    float* out = (float*)d_out;

    cudaFuncSetAttribute(gat_fused_kernel,
                         cudaFuncAttributeMaxDynamicSharedMemorySize, SMEM_FUSED);
    cudaFuncSetAttribute(gemm1_kernel,
                         cudaFuncAttributeMaxDynamicSharedMemorySize, G1_SMEM);

    zero_ctr_kernel<<<1, 1>>>();
    u_kernel<<<64, 256>>>(W, b, a, ab);
    eler_kernel<<<NN / 8, 256>>>(X);
    gemm1_kernel<<<dim3(NN / 64, OUTD / 64), 128, G1_SMEM>>>(b);
    gat_fused_kernel<<<NCTAS, 256, SMEM_FUSED>>>(adj);
    combine_kernel<<<(NN * OUTD / 4) / 256, 256>>>(out);
}

// round 15
// speedup vs baseline: 1.0112x; 1.0112x over previous
#include <cuda_runtime.h>
#include <cuda_fp16.h>
#include <cstdint>

#define NN    8192
#define IND   512
#define OUTD  256
#define BM    64
#define BK    64
#define SPLITS 2
#define JRANGE (NN / SPLITS)      // 4096
#define NTILES (JRANGE / BK)      // 64
#define NRB    (NN / BM)          // 128 row blocks
#define LOG2E 1.4426950408889634f

// ---- fused kernel dynamic smem (bytes) ----
#define SP_OFF   0
#define SP_BUF   8192
#define SH_OFF   16384
#define SH_BUF   32768
#define SER_OFF  81920             // 3 x 512B
#define FLG_OFF  83456             // broadcast slot for arrival order
#define SMEM_FUSED 83472           // 2 CTAs/SM

// XOR swizzle: 16B chunk cb within a row, rotated by row&7
#define SWZ(row, cb) ((((cb) ^ ((row) & 7))) * 16)

// ---------------- scratch ----------------
__device__ __half    g_h16[(size_t)NN * OUTD];            // h fp16 row-major
__device__ __half    g_xh[(size_t)NN * IND];              // X fp16 (written by eler)
__device__ __half    g_wh[(size_t)IND * OUTD];            // W fp16 (written by u)
__device__ float     g_part[(size_t)SPLITS * NN * OUTD];  // split-K partial numerators
__device__ float     g_Lp[SPLITS * NN];                   // split-K partial rowsums
__device__ __align__(16) float2 g_elx[NN];
__device__ __align__(16) float2 g_erx[NN];
__device__ float     g_ul[IND];
__device__ float     g_ur[IND];
__device__ float     g_cb[2];
__device__ uint32_t  g_flag[NRB];                         // combine arbitration

// ---------------- helpers ----------------
__device__ __forceinline__ uint32_t smem_u32(const void* p) {
    return (uint32_t)__cvta_generic_to_shared(p);
}
__device__ __forceinline__ void cp16(void* dst, const void* src) {
    asm volatile("cp.async.cg.shared.global [%0], [%1], 16;" ::
                 "r"(smem_u32(dst)), "l"(src) : "memory");
}
__device__ __forceinline__ void cp_commit() {
    asm volatile("cp.async.commit_group;" ::: "memory");
}
__device__ __forceinline__ void cp_wait0() {
    asm volatile("cp.async.wait_group 0;" ::: "memory");
}
__device__ __forceinline__ float ex2f(float x) {
    float y; asm("ex2.approx.ftz.f32 %0, %1;" : "=f"(y) : "f"(x)); return y;
}
__device__ __forceinline__ uint32_t pack2h(float a, float b) {
    __half2 h = __floats2half2_rn(a, b);
    return *reinterpret_cast<uint32_t*>(&h);
}
__device__ __forceinline__ void ldmA(uint32_t* r, const void* p) {
    uint32_t a = smem_u32(p);
    asm volatile("ldmatrix.sync.aligned.m8n8.x4.shared.b16 {%0,%1,%2,%3}, [%4];"
                 : "=r"(r[0]), "=r"(r[1]), "=r"(r[2]), "=r"(r[3]) : "r"(a));
}
__device__ __forceinline__ void ldmBT(uint32_t* r, const void* p) {
    uint32_t a = smem_u32(p);
    asm volatile("ldmatrix.sync.aligned.m8n8.x4.trans.shared.b16 {%0,%1,%2,%3}, [%4];"
                 : "=r"(r[0]), "=r"(r[1]), "=r"(r[2]), "=r"(r[3]) : "r"(a));
}
__device__ __forceinline__ void mma16816(float* c, const uint32_t* a,
                                         uint32_t b0, uint32_t b1) {
    asm volatile(
        "mma.sync.aligned.m16n8k16.row.col.f32.f16.f16.f32 "
        "{%0,%1,%2,%3},{%4,%5,%6,%7},{%8,%9},{%0,%1,%2,%3};"
        : "+f"(c[0]), "+f"(c[1]), "+f"(c[2]), "+f"(c[3])
        : "r"(a[0]), "r"(a[1]), "r"(a[2]), "r"(a[3]), "r"(b0), "r"(b1));
}

// ---------------- kernel 1: u vectors + W -> fp16 + flag zeroing ----------------
__global__ void __launch_bounds__(256) u_kernel(const float* __restrict__ W,
                                                const float* __restrict__ b,
                                                const float* __restrict__ a,
                                                const float* __restrict__ ab) {
    __shared__ float sa[2 * OUTD];
    const int tid = threadIdx.x;
    if (blockIdx.x == 0 && tid < NRB) g_flag[tid] = 0;   // reset combine flags
    sa[tid]       = a[tid];
    sa[tid + 256] = a[tid + 256];
    __syncthreads();
    const int lane = tid & 31;
    const int k    = blockIdx.x * 8 + (tid >> 5);
    const float* wr = W + (size_t)k * OUTD + lane * 8;
    float4 v0 = *(const float4*)(wr);
    float4 v1 = *(const float4*)(wr + 4);
    {
        uint4 wq;
        wq.x = pack2h(v0.x, v0.y);
        wq.y = pack2h(v0.z, v0.w);
        wq.z = pack2h(v1.x, v1.y);
        wq.w = pack2h(v1.z, v1.w);
        *(uint4*)(g_wh + (size_t)k * OUTD + lane * 8) = wq;
    }
    const float* s0 = sa + lane * 8;
    const float* s1 = sa + OUTD + lane * 8;
    float ul = v0.x * s0[0] + v0.y * s0[1] + v0.z * s0[2] + v0.w * s0[3]
             + v1.x * s0[4] + v1.y * s0[5] + v1.z * s0[6] + v1.w * s0[7];
    float ur = v0.x * s1[0] + v0.y * s1[1] + v0.z * s1[2] + v0.w * s1[3]
             + v1.x * s1[4] + v1.y * s1[5] + v1.z * s1[6] + v1.w * s1[7];
    #pragma unroll
    for (int o = 16; o > 0; o >>= 1) {
        ul += __shfl_xor_sync(0xffffffffu, ul, o);
        ur += __shfl_xor_sync(0xffffffffu, ur, o);
    }
    if (lane == 0) { g_ul[k] = ul; g_ur[k] = ur; }
    if (blockIdx.x == 0 && tid == 0) {
        float bl = 0.f, br = 0.f;
        for (int n = 0; n < OUTD; ++n) {
            bl += b[n] * sa[n];
            br += b[n] * sa[OUTD + n];
        }
        g_cb[0] = bl + ab[0];
        g_cb[1] = br;
    }
}

// ---------------- kernel 2: el/er exps + X -> fp16 ----------------
__global__ void __launch_bounds__(256) eler_kernel(const float* __restrict__ X) {
    __shared__ float sul[IND], sur[IND];
    const int tid = threadIdx.x;
    sul[tid]       = g_ul[tid];
    sul[tid + 256] = g_ul[tid + 256];
    sur[tid]       = g_ur[tid];
    sur[tid + 256] = g_ur[tid + 256];
    __syncthreads();
    const int lane = tid & 31;
    const int w    = tid >> 5;
    const int i    = blockIdx.x * 8 + w;
    const float* xr = X + (size_t)i * IND;
    float dl = 0.f, dr = 0.f;
    #pragma unroll
    for (int q = 0; q < 4; ++q) {
        int c = q * 128 + lane * 4;
        float4 v = *(const float4*)(xr + c);
        uint2 xq;
        xq.x = pack2h(v.x, v.y);
        xq.y = pack2h(v.z, v.w);
        *(uint2*)(g_xh + (size_t)i * IND + c) = xq;
        dl += v.x * sul[c] + v.y * sul[c + 1] + v.z * sul[c + 2] + v.w * sul[c + 3];
        dr += v.x * sur[c] + v.y * sur[c + 1] + v.z * sur[c + 2] + v.w * sur[c + 3];
    }
    #pragma unroll
    for (int o = 16; o > 0; o >>= 1) {
        dl += __shfl_xor_sync(0xffffffffu, dl, o);
        dr += __shfl_xor_sync(0xffffffffu, dr, o);
    }
    if (lane == 0) {
        float el = dl + g_cb[0];
        float er = dr + g_cb[1];
        float2 ev, fv;
        ev.x = ex2f(el * LOG2E - 3.0f);
        ev.y = ex2f(el * (0.2f * LOG2E) - 3.0f);
        fv.x = ex2f(er * LOG2E - 3.0f);
        fv.y = ex2f(er * (0.2f * LOG2E) - 3.0f);
        g_elx[i] = ev;
        g_erx[i] = fv;
    }
}

// ---------------- kernel 3: gemm1 v3 — 64x64 tiles, 512 CTAs, fp16 pipeline ----
#define G1_SMEM 32768
__global__ void __launch_bounds__(128, 4) gemm1_kernel(const float* __restrict__ b) {
    extern __shared__ __align__(1024) char smem[];
    char* sX = smem;
    char* sW = smem + 16384;

    const int tid  = threadIdx.x;
    const int lane = tid & 31;
    const int wid  = tid >> 5;
    const int mblk = blockIdx.x * 64;
    const int nblk = blockIdx.y * 64;
    const int wm   = (wid >> 1) * 32;
    const int wn   = (wid & 1) * 32;

    float acc[2][4][4];
    #pragma unroll
    for (int i = 0; i < 2; ++i)
        #pragma unroll
        for (int j = 0; j < 4; ++j)
            #pragma unroll
            for (int k = 0; k < 4; ++k) acc[i][j][k] = 0.f;

    #pragma unroll
    for (int p = 0; p < 4; ++p) {
        int idx = p * 128 + tid;
        int row = idx >> 3, cb = idx & 7;
        cp16(sX + row * 128 + SWZ(row, cb),
             g_xh + (size_t)(mblk + row) * IND + cb * 8);
        cp16(sW + row * 128 + SWZ(row, cb),
             g_wh + (size_t)row * OUTD + nblk + cb * 8);
    }
    cp_commit();

    for (int ki = 0; ki < IND / BK; ++ki) {
        cp_wait0();
        __syncthreads();

        if (ki + 1 < IND / BK) {
            const int k0 = (ki + 1) * BK;
            const int nb = (ki + 1) & 1;
            #pragma unroll
            for (int p = 0; p < 4; ++p) {
                int idx = p * 128 + tid;
                int row = idx >> 3, cb = idx & 7;
                cp16(sX + nb * 8192 + row * 128 + SWZ(row, cb),
                     g_xh + (size_t)(mblk + row) * IND + k0 + cb * 8);
                cp16(sW + nb * 8192 + row * 128 + SWZ(row, cb),
                     g_wh + (size_t)(k0 + row) * OUTD + nblk + cb * 8);
            }
            cp_commit();
        }

        const char* sXb = sX + (ki & 1) * 8192;
        const char* sWb = sW + (ki & 1) * 8192;
        #pragma unroll
        for (int kk = 0; kk < 4; ++kk) {
            uint32_t A[2][4];
            #pragma unroll
            for (int mf = 0; mf < 2; ++mf) {
                int prow = wm + mf * 16 + (lane & 15);
                ldmA(A[mf], sXb + prow * 128 + SWZ(prow, kk * 2 + (lane >> 4)));
            }
            const int krow = (kk << 4) + (lane & 15);
            const char* wb = sWb + krow * 128;
            #pragma unroll
            for (int nf = 0; nf < 2; ++nf) {
                uint32_t B[4];
                ldmBT(B, wb + SWZ(krow, (wn >> 3) + nf * 2 + (lane >> 4)));
                #pragma unroll
                for (int mf = 0; mf < 2; ++mf) {
                    mma16816(acc[mf][2 * nf],     A[mf], B[0], B[1]);
                    mma16816(acc[mf][2 * nf + 1], A[mf], B[2], B[3]);
                }
            }
        }
    }

    #pragma unroll
    for (int mf = 0; mf < 2; ++mf) {
        int grow = mblk + wm + mf * 16 + (lane >> 2);
        #pragma unroll
        for (int nf = 0; nf < 4; ++nf) {
            int gcol = nblk + wn + nf * 8 + (lane & 3) * 2;
            float b0 = b[gcol], b1 = b[gcol + 1];
            *(__half2*)&g_h16[(size_t)grow * OUTD + gcol] =
                __floats2half2_rn(acc[mf][nf][0] + b0, acc[mf][nf][1] + b1);
            *(__half2*)&g_h16[(size_t)(grow + 8) * OUTD + gcol] =
                __floats2half2_rn(acc[mf][nf][2] + b0, acc[mf][nf][3] + b1);
        }
    }
}

// ---------------- kernel 4: fused attention + inline split-K combine -----------
__global__ void __launch_bounds__(256, 2) gat_fused_kernel(const int* __restrict__ adj,
                                                           float* __restrict__ out) {
    extern __shared__ __align__(1024) char smem[];
    int* sFlg = (int*)(smem + FLG_OFF);

    const int tid  = threadIdx.x;
    const int lane = tid & 31;
    const int wid  = tid >> 5;
    const int s    = blockIdx.x & 1;
    const int rb   = blockIdx.x >> 1;
    const int i0   = rb * BM;
    const int J0   = s * JRANGE;

    const int r  = tid >> 2;
    const int cq = tid & 3;
    const int cg = cq << 4;
    const int* arow = adj + (size_t)(i0 + r) * NN + J0 + cg;

    const float2 ev = g_elx[i0 + r];

    const int wm = (wid >> 2) * 32;
    const int wn = (wid & 3) * 64;

    int4 a[4];
    #pragma unroll
    for (int q = 0; q < 4; ++q) a[q] = __ldcs((const int4*)(arow + 4 * q));

    #pragma unroll
    for (int p = 0; p < 8; ++p) {
        int idx = p * 256 + tid;
        int row = idx >> 5, cb = idx & 31;
        cp16(smem + SH_OFF + row * 512 + SWZ(row, cb),
             g_h16 + (size_t)(J0 + row) * OUTD + cb * 8);
    }
    if (tid < 32) {
        cp16(smem + SER_OFF + tid * 16,       g_erx + J0 + tid * 2);
        cp16(smem + SER_OFF + 512 + tid * 16, g_erx + J0 + BK + tid * 2);
    }
    cp_commit();
    cp_wait0();
    __syncthreads();

    float psum = 0.f;
    {
        const float4* se = (const float4*)(smem + SER_OFF);
        uint32_t pk[8];
        #pragma unroll
        for (int kk = 0; kk < 4; ++kk) {
            float4 f0 = se[(cg + 4 * kk) >> 1];
            float4 f1 = se[((cg + 4 * kk) >> 1) + 1];
            int4 av = a[kk];
            float p0 = fmaxf(ev.x * f0.x, ev.y * f0.y);
            float p1 = fmaxf(ev.x * f0.z, ev.y * f0.w);
            float p2 = fmaxf(ev.x * f1.x, ev.y * f1.y);
            float p3 = fmaxf(ev.x * f1.z, ev.y * f1.w);
            p0 = (av.x > 0) ? p0 : 0.f;
            p1 = (av.y > 0) ? p1 : 0.f;
            p2 = (av.z > 0) ? p2 : 0.f;
            p3 = (av.w > 0) ? p3 : 0.f;
            psum += (p0 + p1) + (p2 + p3);
            pk[2 * kk]     = pack2h(p0, p1);
            pk[2 * kk + 1] = pack2h(p2, p3);
        }
        char* pb = smem + SP_OFF + r * 128;
        *(uint4*)(pb + SWZ(r, 2 * cq))     = make_uint4(pk[0], pk[1], pk[2], pk[3]);
        *(uint4*)(pb + SWZ(r, 2 * cq + 1)) = make_uint4(pk[4], pk[5], pk[6], pk[7]);
    }

    float acc[2][8][4];
    #pragma unroll
    for (int i = 0; i < 2; ++i)
        #pragma unroll
        for (int j = 0; j < 8; ++j)
            #pragma unroll
            for (int k = 0; k < 4; ++k) acc[i][j][k] = 0.f;

    for (int t = 0; t < NTILES; ++t) {
        cp_wait0();
        __syncthreads();

        const bool more = (t + 1 < NTILES);

        if (more) {
            const int jn = J0 + (t + 1) * BK;
            #pragma unroll
            for (int p = 0; p < 8; ++p) {
                int idx = p * 256 + tid;
                int row = idx >> 5, cb = idx & 31;
                cp16(smem + SH_OFF + ((t + 1) & 1) * SH_BUF + row * 512 + SWZ(row, cb),
                     g_h16 + (size_t)(jn + row) * OUTD + cb * 8);
            }
            if (t + 2 < NTILES && tid < 32)
                cp16(smem + SER_OFF + ((t + 2) % 3) * 512 + tid * 16,
                     g_erx + J0 + (t + 2) * BK + tid * 2);
            cp_commit();
        }

        if (more) {
            const int4* an = (const int4*)(arow + (t + 1) * BK);
            #pragma unroll
            for (int q = 0; q < 4; ++q) a[q] = __ldcs(an + q);
        }

        const char*   sPb = smem + SP_OFF + (t & 1) * SP_BUF;
        const char*   sHb = smem + SH_OFF + (t & 1) * SH_BUF;
        const float4* se  = (const float4*)(smem + SER_OFF + ((t + 1) % 3) * 512);

        uint32_t pk[8];

        #pragma unroll
        for (int kk = 0; kk < 4; ++kk) {
            uint32_t A[2][4];
            #pragma unroll
            for (int mf = 0; mf < 2; ++mf) {
                int prow = wm + mf * 16 + (lane & 15);
                ldmA(A[mf], sPb + prow * 128 + SWZ(prow, kk * 2 + (lane >> 4)));
            }
            const int krow = (kk << 4) + (lane & 15);
            const char* hb = sHb + krow * 512;
            #pragma unroll
            for (int nf = 0; nf < 4; ++nf) {
                uint32_t B[4];
                ldmBT(B, hb + SWZ(krow, (wn >> 3) + nf * 2 + (lane >> 4)));
                mma16816(acc[0][2 * nf],     A[0], B[0], B[1]);
                mma16816(acc[0][2 * nf + 1], A[0], B[2], B[3]);
                mma16816(acc[1][2 * nf],     A[1], B[0], B[1]);
                mma16816(acc[1][2 * nf + 1], A[1], B[2], B[3]);
            }

            if (more) {
                float4 f0 = se[(cg + 4 * kk) >> 1];
                float4 f1 = se[((cg + 4 * kk) >> 1) + 1];
                int4 av = a[kk];
                float p0 = fmaxf(ev.x * f0.x, ev.y * f0.y);
                float p1 = fmaxf(ev.x * f0.z, ev.y * f0.w);
                float p2 = fmaxf(ev.x * f1.x, ev.y * f1.y);
                float p3 = fmaxf(ev.x * f1.z, ev.y * f1.w);
                p0 = (av.x > 0) ? p0 : 0.f;
                p1 = (av.y > 0) ? p1 : 0.f;
                p2 = (av.z > 0) ? p2 : 0.f;
                p3 = (av.w > 0) ? p3 : 0.f;
                psum += (p0 + p1) + (p2 + p3);
                pk[2 * kk]     = pack2h(p0, p1);
                pk[2 * kk + 1] = pack2h(p2, p3);
            }
        }

        if (more) {
            char* pb = smem + SP_OFF + ((t + 1) & 1) * SP_BUF + r * 128;
            *(uint4*)(pb + SWZ(r, 2 * cq))     = make_uint4(pk[0], pk[1], pk[2], pk[3]);
            *(uint4*)(pb + SWZ(r, 2 * cq + 1)) = make_uint4(pk[4], pk[5], pk[6], pk[7]);
        }
    }

    // ---- epilogue: write own partials, arbitrate, loser exits / winner combines
    psum += __shfl_xor_sync(0xffffffffu, psum, 1);
    psum += __shfl_xor_sync(0xffffffffu, psum, 2);
    if ((tid & 3) == 0) g_Lp[s * NN + i0 + r] = psum;

    #pragma unroll
    for (int mf = 0; mf < 2; ++mf) {
        int row0 = wm + mf * 16 + (lane >> 2);
        float* d0 = g_part + ((size_t)s * NN + i0 + row0) * OUTD;
        float* d1 = g_part + ((size_t)s * NN + i0 + row0 + 8) * OUTD;
        #pragma unroll
        for (int nf = 0; nf < 8; ++nf) {
            int col = wn + nf * 8 + (lane & 3) * 2;
            *(float2*)(d0 + col) = make_float2(acc[mf][nf][0], acc[mf][nf][1]);
            *(float2*)(d1 + col) = make_float2(acc[mf][nf][2], acc[mf][nf][3]);
        }
    }

    __threadfence();
    __syncthreads();
    if (tid == 0) *sFlg = (int)atomicAdd(&g_flag[rb], 1u);
    __syncthreads();
    if (*sFlg == 0) return;           // first CTA of pair: partials published, done
    __threadfence();                  // acquire: other split's partials now visible

    // second CTA: combine own registers with other split's partials
    const int so = s ^ 1;
    #pragma unroll
    for (int mf = 0; mf < 2; ++mf) {
        #pragma unroll
        for (int h = 0; h < 2; ++h) {
            int row  = wm + mf * 16 + h * 8 + (lane >> 2);
            float inv = 1.0f / (g_Lp[i0 + row] + g_Lp[NN + i0 + row]);
            const float* po = g_part + ((size_t)so * NN + i0 + row) * OUTD;
            float* dst = out + (size_t)(i0 + row) * OUTD;
            #pragma unroll
            for (int nf = 0; nf < 8; ++nf) {
                int col = wn + nf * 8 + (lane & 3) * 2;
                float2 ov = *(const float2*)(po + col);
                float2 res;
                res.x = (acc[mf][nf][2 * h]     + ov.x) * inv;
                res.y = (acc[mf][nf][2 * h + 1] + ov.y) * inv;
                *(float2*)(dst + col) = res;
            }
        }
    }
}

// ---------------- launch ----------------
extern "C" void kernel_launch(void* const* d_in, const int* in_sizes, int n_in,
                              void* d_out, int out_size) {
    const int*   adj = (const int*)d_in[0];
    const float* X   = (const float*)d_in[1];
    const float* W   = (const float*)d_in[2];
    const float* b   = (const float*)d_in[3];
    const float* a   = (const float*)d_in[4];
    const float* ab  = (const float*)d_in[5];
    float* out = (float*)d_out;

    cudaFuncSetAttribute(gat_fused_kernel,
                         cudaFuncAttributeMaxDynamicSharedMemorySize, SMEM_FUSED);
    cudaFuncSetAttribute(gemm1_kernel,
                         cudaFuncAttributeMaxDynamicSharedMemorySize, G1_SMEM);

    u_kernel<<<64, 256>>>(W, b, a, ab);
    eler_kernel<<<NN / 8, 256>>>(X);
    gemm1_kernel<<<dim3(NN / 64, OUTD / 64), 128, G1_SMEM>>>(b);
    gat_fused_kernel<<<NRB * SPLITS, 256, SMEM_FUSED>>>(adj, out);
}

// round 16
// speedup vs baseline: 1.0213x; 1.0100x over previous
#include <cuda_runtime.h>
#include <cuda_fp16.h>
#include <cstdint>

#define NN    8192
#define IND   512
#define OUTD  256
#define BM    64
#define BK    64
#define SPLITS 2
#define JRANGE (NN / SPLITS)      // 4096
#define NTILES (JRANGE / BK)      // 64
#define LOG2E 1.4426950408889634f

// ---- fused kernel dynamic smem (bytes) ----
#define SP_OFF   0
#define SP_BUF   8192
#define SH_OFF   16384
#define SH_BUF   32768
#define SER_OFF  81920             // 3 x 512B
#define SMEM_FUSED 83456           // 2 CTAs/SM

// XOR swizzle: 16B chunk cb within a row, rotated by row&7
#define SWZ(row, cb) ((((cb) ^ ((row) & 7))) * 16)

// ---------------- scratch ----------------
__device__ __half    g_h16[(size_t)NN * OUTD];            // h fp16 row-major
__device__ __half    g_xh[(size_t)NN * IND];              // X fp16 (written by eler)
__device__ __half    g_wh[(size_t)IND * OUTD];            // W fp16 (written by u)
__device__ float     g_part[(size_t)SPLITS * NN * OUTD];  // split-K partial numerators
__device__ float     g_Lp[SPLITS * NN];                   // split-K partial rowsums
__device__ __align__(16) float2 g_elx[NN];
__device__ __align__(16) float2 g_erx[NN];
__device__ float     g_ul[IND];
__device__ float     g_ur[IND];
__device__ float     g_cb[2];

// ---------------- helpers ----------------
__device__ __forceinline__ uint32_t smem_u32(const void* p) {
    return (uint32_t)__cvta_generic_to_shared(p);
}
__device__ __forceinline__ void cp16(void* dst, const void* src) {
    asm volatile("cp.async.cg.shared.global [%0], [%1], 16;" ::
                 "r"(smem_u32(dst)), "l"(src) : "memory");
}
__device__ __forceinline__ void cp_commit() {
    asm volatile("cp.async.commit_group;" ::: "memory");
}
__device__ __forceinline__ void cp_wait0() {
    asm volatile("cp.async.wait_group 0;" ::: "memory");
}
__device__ __forceinline__ float ex2f(float x) {
    float y; asm("ex2.approx.ftz.f32 %0, %1;" : "=f"(y) : "f"(x)); return y;
}
__device__ __forceinline__ uint32_t pack2h(float a, float b) {
    __half2 h = __floats2half2_rn(a, b);
    return *reinterpret_cast<uint32_t*>(&h);
}
// streaming store of float2 (evict-first: data read exactly once later)
__device__ __forceinline__ void stcs2(float* p, float x, float y) {
    float2 v = make_float2(x, y);
    __stcs((float2*)p, v);
}
__device__ __forceinline__ void ldmA(uint32_t* r, const void* p) {
    uint32_t a = smem_u32(p);
    asm volatile("ldmatrix.sync.aligned.m8n8.x4.shared.b16 {%0,%1,%2,%3}, [%4];"
                 : "=r"(r[0]), "=r"(r[1]), "=r"(r[2]), "=r"(r[3]) : "r"(a));
}
__device__ __forceinline__ void ldmBT(uint32_t* r, const void* p) {
    uint32_t a = smem_u32(p);
    asm volatile("ldmatrix.sync.aligned.m8n8.x4.trans.shared.b16 {%0,%1,%2,%3}, [%4];"
                 : "=r"(r[0]), "=r"(r[1]), "=r"(r[2]), "=r"(r[3]) : "r"(a));
}
__device__ __forceinline__ void mma16816(float* c, const uint32_t* a,
                                         uint32_t b0, uint32_t b1) {
    asm volatile(
        "mma.sync.aligned.m16n8k16.row.col.f32.f16.f16.f32 "
        "{%0,%1,%2,%3},{%4,%5,%6,%7},{%8,%9},{%0,%1,%2,%3};"
        : "+f"(c[0]), "+f"(c[1]), "+f"(c[2]), "+f"(c[3])
        : "r"(a[0]), "r"(a[1]), "r"(a[2]), "r"(a[3]), "r"(b0), "r"(b1));
}

// ---------------- kernel 1: u vectors + W -> fp16 ----------------
__global__ void __launch_bounds__(256) u_kernel(const float* __restrict__ W,
                                                const float* __restrict__ b,
                                                const float* __restrict__ a,
                                                const float* __restrict__ ab) {
    __shared__ float sa[2 * OUTD];
    const int tid = threadIdx.x;
    sa[tid]       = a[tid];
    sa[tid + 256] = a[tid + 256];
    __syncthreads();
    const int lane = tid & 31;
    const int k    = blockIdx.x * 8 + (tid >> 5);
    const float* wr = W + (size_t)k * OUTD + lane * 8;
    float4 v0 = *(const float4*)(wr);
    float4 v1 = *(const float4*)(wr + 4);
    {
        uint4 wq;
        wq.x = pack2h(v0.x, v0.y);
        wq.y = pack2h(v0.z, v0.w);
        wq.z = pack2h(v1.x, v1.y);
        wq.w = pack2h(v1.z, v1.w);
        *(uint4*)(g_wh + (size_t)k * OUTD + lane * 8) = wq;
    }
    const float* s0 = sa + lane * 8;
    const float* s1 = sa + OUTD + lane * 8;
    float ul = v0.x * s0[0] + v0.y * s0[1] + v0.z * s0[2] + v0.w * s0[3]
             + v1.x * s0[4] + v1.y * s0[5] + v1.z * s0[6] + v1.w * s0[7];
    float ur = v0.x * s1[0] + v0.y * s1[1] + v0.z * s1[2] + v0.w * s1[3]
             + v1.x * s1[4] + v1.y * s1[5] + v1.z * s1[6] + v1.w * s1[7];
    #pragma unroll
    for (int o = 16; o > 0; o >>= 1) {
        ul += __shfl_xor_sync(0xffffffffu, ul, o);
        ur += __shfl_xor_sync(0xffffffffu, ur, o);
    }
    if (lane == 0) { g_ul[k] = ul; g_ur[k] = ur; }
    if (blockIdx.x == 0 && tid == 0) {
        float bl = 0.f, br = 0.f;
        for (int n = 0; n < OUTD; ++n) {
            bl += b[n] * sa[n];
            br += b[n] * sa[OUTD + n];
        }
        g_cb[0] = bl + ab[0];
        g_cb[1] = br;
    }
}

// ---------------- kernel 2: el/er exps + X -> fp16 ----------------
__global__ void __launch_bounds__(256) eler_kernel(const float* __restrict__ X) {
    __shared__ float sul[IND], sur[IND];
    const int tid = threadIdx.x;
    sul[tid]       = g_ul[tid];
    sul[tid + 256] = g_ul[tid + 256];
    sur[tid]       = g_ur[tid];
    sur[tid + 256] = g_ur[tid + 256];
    __syncthreads();
    const int lane = tid & 31;
    const int w    = tid >> 5;
    const int i    = blockIdx.x * 8 + w;
    const float* xr = X + (size_t)i * IND;
    float dl = 0.f, dr = 0.f;
    #pragma unroll
    for (int q = 0; q < 4; ++q) {
        int c = q * 128 + lane * 4;
        float4 v = *(const float4*)(xr + c);
        uint2 xq;
        xq.x = pack2h(v.x, v.y);
        xq.y = pack2h(v.z, v.w);
        *(uint2*)(g_xh + (size_t)i * IND + c) = xq;
        dl += v.x * sul[c] + v.y * sul[c + 1] + v.z * sul[c + 2] + v.w * sul[c + 3];
        dr += v.x * sur[c] + v.y * sur[c + 1] + v.z * sur[c + 2] + v.w * sur[c + 3];
    }
    #pragma unroll
    for (int o = 16; o > 0; o >>= 1) {
        dl += __shfl_xor_sync(0xffffffffu, dl, o);
        dr += __shfl_xor_sync(0xffffffffu, dr, o);
    }
    if (lane == 0) {
        float el = dl + g_cb[0];
        float er = dr + g_cb[1];
        float2 ev, fv;
        ev.x = ex2f(el * LOG2E - 3.0f);
        ev.y = ex2f(el * (0.2f * LOG2E) - 3.0f);
        fv.x = ex2f(er * LOG2E - 3.0f);
        fv.y = ex2f(er * (0.2f * LOG2E) - 3.0f);
        g_elx[i] = ev;
        g_erx[i] = fv;
    }
}

// ---------------- kernel 3: gemm1 v3 — 64x64 tiles, 512 CTAs, fp16 pipeline ----
#define G1_SMEM 32768
__global__ void __launch_bounds__(128, 4) gemm1_kernel(const float* __restrict__ b) {
    extern __shared__ __align__(1024) char smem[];
    char* sX = smem;
    char* sW = smem + 16384;

    const int tid  = threadIdx.x;
    const int lane = tid & 31;
    const int wid  = tid >> 5;
    const int mblk = blockIdx.x * 64;
    const int nblk = blockIdx.y * 64;
    const int wm   = (wid >> 1) * 32;
    const int wn   = (wid & 1) * 32;

    float acc[2][4][4];
    #pragma unroll
    for (int i = 0; i < 2; ++i)
        #pragma unroll
        for (int j = 0; j < 4; ++j)
            #pragma unroll
            for (int k = 0; k < 4; ++k) acc[i][j][k] = 0.f;

    #pragma unroll
    for (int p = 0; p < 4; ++p) {
        int idx = p * 128 + tid;
        int row = idx >> 3, cb = idx & 7;
        cp16(sX + row * 128 + SWZ(row, cb),
             g_xh + (size_t)(mblk + row) * IND + cb * 8);
        cp16(sW + row * 128 + SWZ(row, cb),
             g_wh + (size_t)row * OUTD + nblk + cb * 8);
    }
    cp_commit();

    for (int ki = 0; ki < IND / BK; ++ki) {
        cp_wait0();
        __syncthreads();

        if (ki + 1 < IND / BK) {
            const int k0 = (ki + 1) * BK;
            const int nb = (ki + 1) & 1;
            #pragma unroll
            for (int p = 0; p < 4; ++p) {
                int idx = p * 128 + tid;
                int row = idx >> 3, cb = idx & 7;
                cp16(sX + nb * 8192 + row * 128 + SWZ(row, cb),
                     g_xh + (size_t)(mblk + row) * IND + k0 + cb * 8);
                cp16(sW + nb * 8192 + row * 128 + SWZ(row, cb),
                     g_wh + (size_t)(k0 + row) * OUTD + nblk + cb * 8);
            }
            cp_commit();
        }

        const char* sXb = sX + (ki & 1) * 8192;
        const char* sWb = sW + (ki & 1) * 8192;
        #pragma unroll
        for (int kk = 0; kk < 4; ++kk) {
            uint32_t A[2][4];
            #pragma unroll
            for (int mf = 0; mf < 2; ++mf) {
                int prow = wm + mf * 16 + (lane & 15);
                ldmA(A[mf], sXb + prow * 128 + SWZ(prow, kk * 2 + (lane >> 4)));
            }
            const int krow = (kk << 4) + (lane & 15);
            const char* wb = sWb + krow * 128;
            #pragma unroll
            for (int nf = 0; nf < 2; ++nf) {
                uint32_t B[4];
                ldmBT(B, wb + SWZ(krow, (wn >> 3) + nf * 2 + (lane >> 4)));
                #pragma unroll
                for (int mf = 0; mf < 2; ++mf) {
                    mma16816(acc[mf][2 * nf],     A[mf], B[0], B[1]);
                    mma16816(acc[mf][2 * nf + 1], A[mf], B[2], B[3]);
                }
            }
        }
    }

    #pragma unroll
    for (int mf = 0; mf < 2; ++mf) {
        int grow = mblk + wm + mf * 16 + (lane >> 2);
        #pragma unroll
        for (int nf = 0; nf < 4; ++nf) {
            int gcol = nblk + wn + nf * 8 + (lane & 3) * 2;
            float b0 = b[gcol], b1 = b[gcol + 1];
            *(__half2*)&g_h16[(size_t)grow * OUTD + gcol] =
                __floats2half2_rn(acc[mf][nf][0] + b0, acc[mf][nf][1] + b1);
            *(__half2*)&g_h16[(size_t)(grow + 8) * OUTD + gcol] =
                __floats2half2_rn(acc[mf][nf][2] + b0, acc[mf][nf][3] + b1);
        }
    }
}

// ---------------- kernel 4: fused attention — R11 verbatim + streaming stores --
__global__ void __launch_bounds__(256, 2) gat_fused_kernel(const int* __restrict__ adj) {
    extern __shared__ __align__(1024) char smem[];

    const int tid  = threadIdx.x;
    const int lane = tid & 31;
    const int wid  = tid >> 5;
    const int s    = blockIdx.x & 1;
    const int rb   = blockIdx.x >> 1;
    const int i0   = rb * BM;
    const int J0   = s * JRANGE;

    const int r  = tid >> 2;
    const int cq = tid & 3;
    const int cg = cq << 4;
    const int* arow = adj + (size_t)(i0 + r) * NN + J0 + cg;

    const float2 ev = g_elx[i0 + r];

    const int wm = (wid >> 2) * 32;
    const int wn = (wid & 3) * 64;

    int4 a[4];
    #pragma unroll
    for (int q = 0; q < 4; ++q) a[q] = __ldcs((const int4*)(arow + 4 * q));

    #pragma unroll
    for (int p = 0; p < 8; ++p) {
        int idx = p * 256 + tid;
        int row = idx >> 5, cb = idx & 31;
        cp16(smem + SH_OFF + row * 512 + SWZ(row, cb),
             g_h16 + (size_t)(J0 + row) * OUTD + cb * 8);
    }
    if (tid < 32) {
        cp16(smem + SER_OFF + tid * 16,       g_erx + J0 + tid * 2);
        cp16(smem + SER_OFF + 512 + tid * 16, g_erx + J0 + BK + tid * 2);
    }
    cp_commit();
    cp_wait0();
    __syncthreads();

    float psum = 0.f;
    {
        const float4* se = (const float4*)(smem + SER_OFF);
        uint32_t pk[8];
        #pragma unroll
        for (int kk = 0; kk < 4; ++kk) {
            float4 f0 = se[(cg + 4 * kk) >> 1];
            float4 f1 = se[((cg + 4 * kk) >> 1) + 1];
            int4 av = a[kk];
            float p0 = fmaxf(ev.x * f0.x, ev.y * f0.y);
            float p1 = fmaxf(ev.x * f0.z, ev.y * f0.w);
            float p2 = fmaxf(ev.x * f1.x, ev.y * f1.y);
            float p3 = fmaxf(ev.x * f1.z, ev.y * f1.w);
            p0 = (av.x > 0) ? p0 : 0.f;
            p1 = (av.y > 0) ? p1 : 0.f;
            p2 = (av.z > 0) ? p2 : 0.f;
            p3 = (av.w > 0) ? p3 : 0.f;
            psum += (p0 + p1) + (p2 + p3);
            pk[2 * kk]     = pack2h(p0, p1);
            pk[2 * kk + 1] = pack2h(p2, p3);
        }
        char* pb = smem + SP_OFF + r * 128;
        *(uint4*)(pb + SWZ(r, 2 * cq))     = make_uint4(pk[0], pk[1], pk[2], pk[3]);
        *(uint4*)(pb + SWZ(r, 2 * cq + 1)) = make_uint4(pk[4], pk[5], pk[6], pk[7]);
    }

    float acc[2][8][4];
    #pragma unroll
    for (int i = 0; i < 2; ++i)
        #pragma unroll
        for (int j = 0; j < 8; ++j)
            #pragma unroll
            for (int k = 0; k < 4; ++k) acc[i][j][k] = 0.f;

    for (int t = 0; t < NTILES; ++t) {
        cp_wait0();
        __syncthreads();

        const bool more = (t + 1 < NTILES);

        if (more) {
            const int jn = J0 + (t + 1) * BK;
            #pragma unroll
            for (int p = 0; p < 8; ++p) {
                int idx = p * 256 + tid;
                int row = idx >> 5, cb = idx & 31;
                cp16(smem + SH_OFF + ((t + 1) & 1) * SH_BUF + row * 512 + SWZ(row, cb),
                     g_h16 + (size_t)(jn + row) * OUTD + cb * 8);
            }
            if (t + 2 < NTILES && tid < 32)
                cp16(smem + SER_OFF + ((t + 2) % 3) * 512 + tid * 16,
                     g_erx + J0 + (t + 2) * BK + tid * 2);
            cp_commit();
        }

        if (more) {
            const int4* an = (const int4*)(arow + (t + 1) * BK);
            #pragma unroll
            for (int q = 0; q < 4; ++q) a[q] = __ldcs(an + q);
        }

        const char*   sPb = smem + SP_OFF + (t & 1) * SP_BUF;
        const char*   sHb = smem + SH_OFF + (t & 1) * SH_BUF;
        const float4* se  = (const float4*)(smem + SER_OFF + ((t + 1) % 3) * 512);

        uint32_t pk[8];

        #pragma unroll
        for (int kk = 0; kk < 4; ++kk) {
            uint32_t A[2][4];
            #pragma unroll
            for (int mf = 0; mf < 2; ++mf) {
                int prow = wm + mf * 16 + (lane & 15);
                ldmA(A[mf], sPb + prow * 128 + SWZ(prow, kk * 2 + (lane >> 4)));
            }
            const int krow = (kk << 4) + (lane & 15);
            const char* hb = sHb + krow * 512;
            #pragma unroll
            for (int nf = 0; nf < 4; ++nf) {
                uint32_t B[4];
                ldmBT(B, hb + SWZ(krow, (wn >> 3) + nf * 2 + (lane >> 4)));
                mma16816(acc[0][2 * nf],     A[0], B[0], B[1]);
                mma16816(acc[0][2 * nf + 1], A[0], B[2], B[3]);
                mma16816(acc[1][2 * nf],     A[1], B[0], B[1]);
                mma16816(acc[1][2 * nf + 1], A[1], B[2], B[3]);
            }

            if (more) {
                float4 f0 = se[(cg + 4 * kk) >> 1];
                float4 f1 = se[((cg + 4 * kk) >> 1) + 1];
                int4 av = a[kk];
                float p0 = fmaxf(ev.x * f0.x, ev.y * f0.y);
                float p1 = fmaxf(ev.x * f0.z, ev.y * f0.w);
                float p2 = fmaxf(ev.x * f1.x, ev.y * f1.y);
                float p3 = fmaxf(ev.x * f1.z, ev.y * f1.w);
                p0 = (av.x > 0) ? p0 : 0.f;
                p1 = (av.y > 0) ? p1 : 0.f;
                p2 = (av.z > 0) ? p2 : 0.f;
                p3 = (av.w > 0) ? p3 : 0.f;
                psum += (p0 + p1) + (p2 + p3);
                pk[2 * kk]     = pack2h(p0, p1);
                pk[2 * kk + 1] = pack2h(p2, p3);
            }
        }

        if (more) {
            char* pb = smem + SP_OFF + ((t + 1) & 1) * SP_BUF + r * 128;
            *(uint4*)(pb + SWZ(r, 2 * cq))     = make_uint4(pk[0], pk[1], pk[2], pk[3]);
            *(uint4*)(pb + SWZ(r, 2 * cq + 1)) = make_uint4(pk[4], pk[5], pk[6], pk[7]);
        }
    }

    psum += __shfl_xor_sync(0xffffffffu, psum, 1);
    psum += __shfl_xor_sync(0xffffffffu, psum, 2);
    if ((tid & 3) == 0) g_Lp[s * NN + i0 + r] = psum;

    // partial numerators: streaming stores (read once by combine, then dead)
    #pragma unroll
    for (int mf = 0; mf < 2; ++mf) {
        int row0 = wm + mf * 16 + (lane >> 2);
        float* d0 = g_part + ((size_t)s * NN + i0 + row0) * OUTD;
        float* d1 = g_part + ((size_t)s * NN + i0 + row0 + 8) * OUTD;
        #pragma unroll
        for (int nf = 0; nf < 8; ++nf) {
            int col = wn + nf * 8 + (lane & 3) * 2;
            stcs2(d0 + col, acc[mf][nf][0], acc[mf][nf][1]);
            stcs2(d1 + col, acc[mf][nf][2], acc[mf][nf][3]);
        }
    }
}

// ---------------- kernel 5: combine split-K partials ----------------
__global__ void __launch_bounds__(256) combine_kernel(float* __restrict__ out) {
    const int gid = blockIdx.x * 256 + threadIdx.x;
    const int row = gid >> 6;
    const int c   = (gid & 63) * 4;
    const float4 x0 = __ldcs((const float4*)(g_part + (size_t)row * OUTD + c));
    const float4 x1 = __ldcs((const float4*)(g_part + (size_t)NN * OUTD + (size_t)row * OUTD + c));
    const float inv = 1.0f / (g_Lp[row] + g_Lp[NN + row]);
    float4 o;
    o.x = (x0.x + x1.x) * inv;
    o.y = (x0.y + x1.y) * inv;
    o.z = (x0.z + x1.z) * inv;
    o.w = (x0.w + x1.w) * inv;
    __stcs((float4*)(out + (size_t)row * OUTD + c), o);
}

// ---------------- launch ----------------
extern "C" void kernel_launch(void* const* d_in, const int* in_sizes, int n_in,
                              void* d_out, int out_size) {
    const int*   adj = (const int*)d_in[0];
    const float* X   = (const float*)d_in[1];
    const float* W   = (const float*)d_in[2];
    const float* b   = (const float*)d_in[3];
    const float* a   = (const float*)d_in[4];
    const float* ab  = (const float*)d_in[5];
    float* out = (float*)d_out;

    cudaFuncSetAttribute(gat_fused_kernel,
                         cudaFuncAttributeMaxDynamicSharedMemorySize, SMEM_FUSED);
    cudaFuncSetAttribute(gemm1_kernel,
                         cudaFuncAttributeMaxDynamicSharedMemorySize, G1_SMEM);

    u_kernel<<<64, 256>>>(W, b, a, ab);
    eler_kernel<<<NN / 8, 256>>>(X);
    gemm1_kernel<<<dim3(NN / 64, OUTD / 64), 128, G1_SMEM>>>(b);
    gat_fused_kernel<<<(NN / BM) * SPLITS, 256, SMEM_FUSED>>>(adj);
    combine_kernel<<<(NN * OUTD / 4) / 256, 256>>>(out);
}